// round 6
// baseline (speedup 1.0000x reference)
#include <cuda_runtime.h>

#define WS 8
#define BB 64
#define TT 256
#define HH 64
#define NW 248

typedef unsigned long long u64;

__device__ __forceinline__ void fma2(u64 &acc, u64 a, u64 b) {
    asm("fma.rn.f32x2 %0, %1, %2, %0;" : "+l"(acc) : "l"(a), "l"(b));
}
__device__ __forceinline__ void add2(u64 &a, u64 b) {
    asm("add.rn.f32x2 %0, %1, %2;" : "=l"(a) : "l"(a), "l"(b));
}
__device__ __forceinline__ u64 pack2(float a, float b) {
    u64 r; asm("mov.b64 %0, {%1, %2};" : "=l"(r) : "f"(a), "f"(b)); return r;
}
__device__ __forceinline__ float lo_f(u64 v) { return __uint_as_float((unsigned)v); }
__device__ __forceinline__ float hi_f(u64 v) { return __uint_as_float((unsigned)(v >> 32)); }
__device__ __forceinline__ float tanh_ap(float x) {
    float y; asm("tanh.approx.f32 %0, %1;" : "=f"(y) : "f"(x)); return y;
}
__device__ __forceinline__ float sigm(float x) {
    return fmaf(0.5f, tanh_ap(0.5f * x), 0.5f);
}
__device__ __forceinline__ u64 shflx(u64 v, int mask) {
    unsigned lo = (unsigned)v, hi = (unsigned)(v >> 32);
    lo = __shfl_xor_sync(0xffffffffu, lo, mask);
    hi = __shfl_xor_sync(0xffffffffu, hi, mask);
    return ((u64)hi << 32) | lo;
}

// Fused dual-element GEMV slice: each weight register feeds elem A and elem B.
__device__ __forceinline__ void dotAB(u64 aA[4], u64 aB[4],
                                      const float* __restrict__ hA,
                                      const float* __restrict__ hB,
                                      const u64 (&w)[4][4][2], int sl) {
    #pragma unroll
    for (int c = 0; c < 4; c++) {
        ulonglong2 hvA = *(const ulonglong2*)(hA + 16 * c + 4 * sl);
        ulonglong2 hvB = *(const ulonglong2*)(hB + 16 * c + 4 * sl);
        #pragma unroll
        for (int g = 0; g < 4; g++) {
            fma2(aA[g], hvA.x, w[g][c][0]);
            fma2(aA[g], hvA.y, w[g][c][1]);
            fma2(aB[g], hvB.x, w[g][c][0]);
            fma2(aB[g], hvB.y, w[g][c][1]);
        }
    }
}

// cross-slice reduce + bias + LSTM cell; all 4 lanes of a group replicate result.
__device__ __forceinline__ float cell_epi(u64 acc[4], u64 X0, u64 X1,
                                          u64 b0, u64 b1, float &c, bool first) {
    u64 A = X0, B = X1;
    add2(A, pack2(lo_f(acc[0]) + hi_f(acc[0]), lo_f(acc[1]) + hi_f(acc[1])));
    add2(B, pack2(lo_f(acc[2]) + hi_f(acc[2]), lo_f(acc[3]) + hi_f(acc[3])));
    add2(A, shflx(A, 1)); add2(B, shflx(B, 1));
    add2(A, shflx(A, 2)); add2(B, shflx(B, 2));
    add2(A, b0); add2(B, b1);
    float ig = sigm(lo_f(A)), fg = sigm(hi_f(A));
    float gg = tanh_ap(lo_f(B)), og = sigm(hi_f(B));
    c = first ? ig * gg : fmaf(fg, c, ig * gg);
    return og * tanh_ap(c);
}

__device__ __forceinline__ float xin_value(const float* trajs, const float* preds,
                                           int w, int s, int f) {
    if (w == 0) return trajs[s * 4 + f];
    if (w < WS) {
        if (s < WS - w) return trajs[(w + s) * 4 + f];
        return (f < 2) ? trajs[(2 * w + s - 1) * 4 + f]
                       : preds[(w + s - WS) * 2 + (f - 2)];
    }
    return (f < 2) ? trajs[(w + s) * 4 + f]
                   : preds[(w + s - WS) * 2 + (f - 2)];
}

__global__ __launch_bounds__(256, 1)
void or_lstm_kernel(const float* __restrict__ traj,
                    const float* __restrict__ Wih0, const float* __restrict__ Whh0,
                    const float* __restrict__ bih0, const float* __restrict__ bhh0,
                    const float* __restrict__ Wih1, const float* __restrict__ Whh1,
                    const float* __restrict__ bih1, const float* __restrict__ bhh1,
                    const float* __restrict__ Wlin, const float* __restrict__ blin,
                    float* __restrict__ out)
{
    const int bA  = blockIdx.x * 2;
    const int bBt = bA + 1;
    const int tid = threadIdx.x;
    const int m   = tid >> 2;   // h-index this group owns
    const int sl  = tid & 3;    // k-slice within the group

    __shared__ __align__(16) float trajsA[TT * 4];
    __shared__ __align__(16) float trajsB[TT * 4];
    __shared__ __align__(16) float h0A[2][HH], h1A[2][HH];
    __shared__ __align__(16) float h0B[2][HH], h1B[2][HH];
    __shared__ __align__(16) float xinA[WS][4], xinB[WS][4];
    __shared__ float predsA[NW * 2], predsB[NW * 2];
    __shared__ float redA[128], redB[128];
    __shared__ float wlin_s[128];
    __shared__ float blin_s[2];

    for (int i = tid; i < TT * 4; i += 256) {
        trajsA[i] = traj[bA  * TT * 4 + i];
        trajsB[i] = traj[bBt * TT * 4 + i];
    }
    if (tid < 128) wlin_s[tid] = Wlin[tid];
    if (tid < 2)   blin_s[tid] = blin[tid];

    // ---- shared-model weights -> registers (same regs serve both elems) ----
    u64 whh0p[4][4][2], wih1p[4][4][2], whh1p[4][4][2];
    u64 wih0p0, wih0p1, b0p0, b0p1, b1p0, b1p1;
    {
        float wi[4], bb0[4], bb1[4];
        #pragma unroll
        for (int g = 0; g < 4; g++) {
            const int rg = 64 * g + m;
            wi[g]  = Wih0[rg * 4 + sl];
            bb0[g] = bih0[rg] + bhh0[rg];
            bb1[g] = bih1[rg] + bhh1[rg];
            #pragma unroll
            for (int c = 0; c < 4; c++) {
                const int k0 = 16 * c + 4 * sl;
                ulonglong2 v0 = *(const ulonglong2*)(Whh0 + rg * HH + k0);
                whh0p[g][c][0] = v0.x; whh0p[g][c][1] = v0.y;
                ulonglong2 v1 = *(const ulonglong2*)(Wih1 + rg * HH + k0);
                wih1p[g][c][0] = v1.x; wih1p[g][c][1] = v1.y;
                ulonglong2 v2 = *(const ulonglong2*)(Whh1 + rg * HH + k0);
                whh1p[g][c][0] = v2.x; whh1p[g][c][1] = v2.y;
            }
        }
        wih0p0 = pack2(wi[0], wi[1]);  wih0p1 = pack2(wi[2], wi[3]);
        b0p0 = pack2(bb0[0], bb0[1]);  b0p1 = pack2(bb0[2], bb0[3]);
        b1p0 = pack2(bb1[0], bb1[1]);  b1p1 = pack2(bb1[2], bb1[3]);
    }

    float c0A = 0.f, c1A = 0.f, h0vA = 0.f, h1vA = 0.f;
    float c0B = 0.f, c1B = 0.f, h0vB = 0.f, h1vB = 0.f;
    __syncthreads();   // trajs staged

    for (int w = 0; w < NW; w++) {
        // ---- build all 8 input rows for this window, both elems ----
        if (tid < 32) {
            const int s = tid >> 2, f = tid & 3;
            xinA[s][f] = xin_value(trajsA, predsA, w, s, f);
        } else if (tid < 64) {
            const int idx = tid - 32, s = idx >> 2, f = idx & 3;
            xinB[s][f] = xin_value(trajsB, predsB, w, s, f);
        }
        __syncthreads();

        // ---- s = 0 (zero initial state) ----
        {
            float xsA = xinA[0][sl], xsB = xinB[0][sl];
            u64 xxA = pack2(xsA, xsA), xxB = pack2(xsB, xsB);
            u64 X0A = 0, X1A = 0, X0B = 0, X1B = 0;
            fma2(X0A, xxA, wih0p0); fma2(X1A, xxA, wih0p1);
            fma2(X0B, xxB, wih0p0); fma2(X1B, xxB, wih0p1);
            u64 zA[4] = {0,0,0,0}, zB[4] = {0,0,0,0};
            h0vA = cell_epi(zA, X0A, X1A, b0p0, b0p1, c0A, true);
            h0vB = cell_epi(zB, X0B, X1B, b0p0, b0p1, c0B, true);
            if (sl == 0) { h0A[0][m] = h0vA; h0B[0][m] = h0vB; }
            __syncthreads();
            u64 aA[4] = {0,0,0,0}, aB[4] = {0,0,0,0};
            dotAB(aA, aB, h0A[0], h0B[0], wih1p, sl);
            h1vA = cell_epi(aA, 0, 0, b1p0, b1p1, c1A, true);
            h1vB = cell_epi(aB, 0, 0, b1p0, b1p1, c1B, true);
            if (sl == 0) { h1A[0][m] = h1vA; h1B[0][m] = h1vB; }
        }

        // ---- s = 1..7 : one barrier per step ----
        for (int s = 1; s < WS; s++) {
            const int pc = s & 1, pp = pc ^ 1;
            float xsA = xinA[s][sl], xsB = xinB[s][sl];
            u64 xxA = pack2(xsA, xsA), xxB = pack2(xsB, xsB);
            u64 aA[4] = {0,0,0,0}, aB[4] = {0,0,0,0};
            u64 X0A = 0, X1A = 0, X0B = 0, X1B = 0;
            fma2(X0A, xxA, wih0p0); fma2(X1A, xxA, wih0p1);
            fma2(X0B, xxB, wih0p0); fma2(X1B, xxB, wih0p1);
            dotAB(aA, aB, h0A[pp], h0B[pp], whh0p, sl);
            h0vA = cell_epi(aA, X0A, X1A, b0p0, b0p1, c0A, false);
            h0vB = cell_epi(aB, X0B, X1B, b0p0, b0p1, c0B, false);
            if (sl == 0) { h0A[pc][m] = h0vA; h0B[pc][m] = h0vB; }
            __syncthreads();
            u64 gA[4] = {0,0,0,0}, gB[4] = {0,0,0,0};
            dotAB(gA, gB, h0A[pc], h0B[pc], wih1p, sl);
            dotAB(gA, gB, h1A[pp], h1B[pp], whh1p, sl);
            h1vA = cell_epi(gA, 0, 0, b1p0, b1p1, c1A, false);
            h1vB = cell_epi(gB, 0, 0, b1p0, b1p1, c1B, false);
            if (sl == 0) { h1A[pc][m] = h1vA; h1B[pc][m] = h1vB; }
        }
        __syncthreads();   // h1(7) visible (parity 1)

        // ---- prediction: p[w] = p[w-1] + Wlin·h1 + blin, both elems ----
        {
            const int half = tid & 127, r = half >> 6, k = half & 63;
            if (tid < 128) redA[half] = wlin_s[r * 64 + k] * h1A[1][k];
            else           redB[half] = wlin_s[r * 64 + k] * h1B[1][k];
        }
        __syncthreads();
        if (tid < 2) {
            float d = blin_s[tid];
            #pragma unroll
            for (int k = 0; k < 64; k++) d += redA[tid * 64 + k];
            const float prev = (w == 0) ? trajsA[7 * 4 + 2 + tid]
                                        : predsA[(w - 1) * 2 + tid];
            const float p = prev + d;
            predsA[w * 2 + tid] = p;
            out[(bA * NW + w) * 2 + tid] = p;
        } else if (tid >= 4 && tid < 6) {
            const int r = tid - 4;
            float d = blin_s[r];
            #pragma unroll
            for (int k = 0; k < 64; k++) d += redB[r * 64 + k];
            const float prev = (w == 0) ? trajsB[7 * 4 + 2 + r]
                                        : predsB[(w - 1) * 2 + r];
            const float p = prev + d;
            predsB[w * 2 + r] = p;
            out[(bBt * NW + w) * 2 + r] = p;
        }
        __syncthreads();
    }

    // ---- final states: h[2,B,H] then c[2,B,H] ----
    if (sl == 0) {
        const int base = BB * NW * 2;
        out[base + 0 * BB * HH + bA  * HH + m] = h0vA;
        out[base + 1 * BB * HH + bA  * HH + m] = h1vA;
        out[base + 2 * BB * HH + bA  * HH + m] = c0A;
        out[base + 3 * BB * HH + bA  * HH + m] = c1A;
        out[base + 0 * BB * HH + bBt * HH + m] = h0vB;
        out[base + 1 * BB * HH + bBt * HH + m] = h1vB;
        out[base + 2 * BB * HH + bBt * HH + m] = c0B;
        out[base + 3 * BB * HH + bBt * HH + m] = c1B;
    }
}

extern "C" void kernel_launch(void* const* d_in, const int* in_sizes, int n_in,
                              void* d_out, int out_size) {
    const float* traj = (const float*)d_in[0];
    const float* Wih0 = (const float*)d_in[1];
    const float* Whh0 = (const float*)d_in[2];
    const float* bih0 = (const float*)d_in[3];
    const float* bhh0 = (const float*)d_in[4];
    const float* Wih1 = (const float*)d_in[5];
    const float* Whh1 = (const float*)d_in[6];
    const float* bih1 = (const float*)d_in[7];
    const float* bhh1 = (const float*)d_in[8];
    const float* Wlin = (const float*)d_in[9];
    const float* blin = (const float*)d_in[10];

    or_lstm_kernel<<<BB / 2, 256>>>(traj, Wih0, Whh0, bih0, bhh0,
                                    Wih1, Whh1, bih1, bhh1,
                                    Wlin, blin, (float*)d_out);
}

// round 7
// speedup vs baseline: 1.9585x; 1.9585x over previous
#include <cuda_runtime.h>

#define WS 8
#define BB 64
#define TT 256
#define HH 64
#define NW 248

typedef unsigned long long u64;

__device__ __forceinline__ void fma2(u64 &acc, u64 a, u64 b) {
    asm("fma.rn.f32x2 %0, %1, %2, %0;" : "+l"(acc) : "l"(a), "l"(b));
}
__device__ __forceinline__ void add2(u64 &a, u64 b) {
    asm("add.rn.f32x2 %0, %1, %2;" : "=l"(a) : "l"(a), "l"(b));
}
__device__ __forceinline__ u64 pack2(float a, float b) {
    u64 r; asm("mov.b64 %0, {%1, %2};" : "=l"(r) : "f"(a), "f"(b)); return r;
}
__device__ __forceinline__ float lo_f(u64 v) { return __uint_as_float((unsigned)v); }
__device__ __forceinline__ float hi_f(u64 v) { return __uint_as_float((unsigned)(v >> 32)); }
__device__ __forceinline__ float hsum(u64 v) { return lo_f(v) + hi_f(v); }
__device__ __forceinline__ float tanh_ap(float x) {
    float y; asm("tanh.approx.f32 %0, %1;" : "=f"(y) : "f"(x)); return y;
}
__device__ __forceinline__ u64 shflx(u64 v, int mask) {
    unsigned lo = (unsigned)v, hi = (unsigned)(v >> 32);
    lo = __shfl_xor_sync(0xffffffffu, lo, mask);
    hi = __shfl_xor_sync(0xffffffffu, hi, mask);
    return ((u64)hi << 32) | lo;
}
__device__ __forceinline__ u64 reduce_pair(u64 v) {
    add2(v, shflx(v, 1)); add2(v, shflx(v, 2)); return v;
}

// acc[g] += W[g] · h_slice (16 k-elements, chunks 16c+4sl)
__device__ __forceinline__ void dot64(u64 acc[4], const float* __restrict__ hbuf,
                                      const u64 (&w)[4][4][2], int sl) {
    #pragma unroll
    for (int c = 0; c < 4; c++) {
        ulonglong2 hv = *(const ulonglong2*)(hbuf + 16 * c + 4 * sl);
        #pragma unroll
        for (int g = 0; g < 4; g++) {
            fma2(acc[g], hv.x, w[g][c][0]);
            fma2(acc[g], hv.y, w[g][c][1]);
        }
    }
}

// lane sl computes ONLY its own gate's activation (1 MUFU, uniform instr)
__device__ __forceinline__ float gate_act(u64 A, u64 B, int sl, float km, float kb) {
    float arg = (sl & 2) ? ((sl & 1) ? hi_f(B) : lo_f(B))
                         : ((sl & 1) ? hi_f(A) : lo_f(A));
    return fmaf(km, tanh_ap(km * arg), kb);
}
// gather gates into lane 0 of each 4-lane group; c/h valid in lane 0 only
__device__ __forceinline__ float cell_from_act(float act, float &c, bool first) {
    float f_ = __shfl_down_sync(0xffffffffu, act, 1);
    float g_ = __shfl_down_sync(0xffffffffu, act, 2);
    float o_ = __shfl_down_sync(0xffffffffu, act, 3);
    c = first ? act * g_ : fmaf(f_, c, act * g_);
    return o_ * tanh_ap(c);
}

__device__ __forceinline__ float xin_value(const float* trajs, const float* preds,
                                           int w, int s, int f) {
    if (w == 0) return trajs[s * 4 + f];
    if (w < WS) {
        if (s < WS - w) return trajs[(w + s) * 4 + f];
        return (f < 2) ? trajs[(2 * w + s - 1) * 4 + f]
                       : preds[(w + s - WS) * 2 + (f - 2)];
    }
    return (f < 2) ? trajs[(w + s) * 4 + f]
                   : preds[(w + s - WS) * 2 + (f - 2)];
}

__global__ __launch_bounds__(256, 1)
void or_lstm_kernel(const float* __restrict__ traj,
                    const float* __restrict__ Wih0, const float* __restrict__ Whh0,
                    const float* __restrict__ bih0, const float* __restrict__ bhh0,
                    const float* __restrict__ Wih1, const float* __restrict__ Whh1,
                    const float* __restrict__ bih1, const float* __restrict__ bhh1,
                    const float* __restrict__ Wlin, const float* __restrict__ blin,
                    float* __restrict__ out)
{
    const int b    = blockIdx.x;
    const int tid  = threadIdx.x;
    const int m    = tid >> 2;    // h-index this group owns
    const int sl   = tid & 3;     // k-slice / gate-lane within the group
    const int wid  = tid >> 5;
    const int lane = tid & 31;

    __shared__ __align__(16) float trajs[TT * 4];
    __shared__ __align__(16) float h0s[2][HH], h1s[2][HH];
    __shared__ __align__(16) u64 xgb01[WS][HH], xgb23[WS][HH];  // bias0 + Wih0·x(s)
    __shared__ __align__(16) u64 wp01s[HH * 4], wp23s[HH * 4];
    __shared__ __align__(16) u64 bp01s[HH], bp23s[HH];
    __shared__ float preds[NW * 2];
    __shared__ float predpart[16];
    __shared__ float blin_s[2];

    for (int i = tid; i < TT * 4; i += 256) trajs[i] = traj[b * TT * 4 + i];
    if (tid < 2) blin_s[tid] = blin[tid];
    {   // Wih0 / bias0 tables packed by gate pairs (i,f) and (g,o)
        const int mm = tid >> 2, f = tid & 3;
        wp01s[tid] = pack2(Wih0[(mm)       * 4 + f], Wih0[(64 + mm)  * 4 + f]);
        wp23s[tid] = pack2(Wih0[(128 + mm) * 4 + f], Wih0[(192 + mm) * 4 + f]);
    }
    if (tid < 64) {
        bp01s[tid] = pack2(bih0[tid] + bhh0[tid],          bih0[64 + tid] + bhh0[64 + tid]);
        bp23s[tid] = pack2(bih0[128 + tid] + bhh0[128 + tid], bih0[192 + tid] + bhh0[192 + tid]);
    }

    // ---- recurrent weights -> registers (thread (m,sl): 4 gate rows, 16-k slice) ----
    u64 whh0p[4][4][2], wih1p[4][4][2], whh1p[4][4][2];
    u64 b1p0, b1p1;
    {
        float bb1[4];
        #pragma unroll
        for (int g = 0; g < 4; g++) {
            const int rg = 64 * g + m;
            bb1[g] = bih1[rg] + bhh1[rg];
            #pragma unroll
            for (int c = 0; c < 4; c++) {
                const int k0 = 16 * c + 4 * sl;
                ulonglong2 v0 = *(const ulonglong2*)(Whh0 + rg * HH + k0);
                whh0p[g][c][0] = v0.x; whh0p[g][c][1] = v0.y;
                ulonglong2 v1 = *(const ulonglong2*)(Wih1 + rg * HH + k0);
                wih1p[g][c][0] = v1.x; wih1p[g][c][1] = v1.y;
                ulonglong2 v2 = *(const ulonglong2*)(Whh1 + rg * HH + k0);
                whh1p[g][c][0] = v2.x; whh1p[g][c][1] = v2.y;
            }
        }
        b1p0 = pack2(bb1[0], bb1[1]); b1p1 = pack2(bb1[2], bb1[3]);
    }
    const float wlreg = (sl < 2) ? Wlin[sl * 64 + m] : 0.0f;
    const float km = (sl == 2) ? 1.0f : 0.5f;   // tanh gate vs sigmoid gates
    const float kb = (sl == 2) ? 0.0f : 0.5f;

    float c0 = 0.f, c1 = 0.f, h0v = 0.f, h1v = 0.f;

    // xgb row builder: warp computes one (w,s) row; lane handles m=lane, lane+32
    auto xgb_row = [&](int w, int s) {
        float xf = 0.0f;
        if (lane < 4) xf = xin_value(trajs, preds, w, s, lane);
        u64 px[4];
        #pragma unroll
        for (int f = 0; f < 4; f++) {
            float x = __shfl_sync(0xffffffffu, xf, f);
            px[f] = pack2(x, x);
        }
        #pragma unroll
        for (int r = 0; r < 2; r++) {
            const int mm = lane + 32 * r;
            u64 a01 = bp01s[mm], a23 = bp23s[mm];
            #pragma unroll
            for (int f = 0; f < 4; f++) {
                fma2(a01, px[f], wp01s[mm * 4 + f]);
                fma2(a23, px[f], wp23s[mm * 4 + f]);
            }
            xgb01[s][mm] = a01; xgb23[s][mm] = a23;
        }
    };

    __syncthreads();          // trajs + tables staged
    xgb_row(0, wid);          // all 8 rows of window 0 (pure traj)
    __syncthreads();

    for (int w = 0; w < NW; w++) {
        // ===== phase 0: P0(0)  [+ side: xgb row 7 of this window, needs pred[w-1]]
        {
            u64 A0 = xgb01[0][m], B0 = xgb23[0][m];
            float a0 = gate_act(A0, B0, sl, km, kb);
            h0v = cell_from_act(a0, c0, true);
            if (sl == 0) h0s[0][m] = h0v;
            if (w > 0 && wid == 7) xgb_row(w, 7);
        }
        __syncthreads();

        // ===== phase 1: P1(0) {no h1 term, first} + P0(1)
        {
            u64 acc1[4] = {0,0,0,0};
            dot64(acc1, h0s[0], wih1p, sl);
            u64 acc0[4] = {0,0,0,0};
            dot64(acc0, h0s[0], whh0p, sl);
            u64 A1 = reduce_pair(pack2(hsum(acc1[0]), hsum(acc1[1])));
            u64 B1 = reduce_pair(pack2(hsum(acc1[2]), hsum(acc1[3])));
            add2(A1, b1p0); add2(B1, b1p1);
            u64 A0 = reduce_pair(pack2(hsum(acc0[0]), hsum(acc0[1])));
            u64 B0 = reduce_pair(pack2(hsum(acc0[2]), hsum(acc0[3])));
            add2(A0, xgb01[1][m]); add2(B0, xgb23[1][m]);
            float a1 = gate_act(A1, B1, sl, km, kb);
            h1v = cell_from_act(a1, c1, true);
            if (sl == 0) h1s[0][m] = h1v;
            float a0 = gate_act(A0, B0, sl, km, kb);
            h0v = cell_from_act(a0, c0, false);
            if (sl == 0) h0s[1][m] = h0v;
        }
        __syncthreads();

        // ===== phases 2..7: P1(s-1) + P0(s), one barrier each
        #pragma unroll 2
        for (int s = 2; s < WS; s++) {
            const int ps = s & 1, pp = ps ^ 1;
            u64 acc1[4] = {0,0,0,0};
            dot64(acc1, h0s[pp], wih1p, sl);     // h0(s-1)
            dot64(acc1, h1s[ps], whh1p, sl);     // h1(s-2): (s-2)&1 == s&1
            u64 acc0[4] = {0,0,0,0};
            dot64(acc0, h0s[pp], whh0p, sl);     // h0(s-1)
            u64 A1 = reduce_pair(pack2(hsum(acc1[0]), hsum(acc1[1])));
            u64 B1 = reduce_pair(pack2(hsum(acc1[2]), hsum(acc1[3])));
            add2(A1, b1p0); add2(B1, b1p1);
            u64 A0 = reduce_pair(pack2(hsum(acc0[0]), hsum(acc0[1])));
            u64 B0 = reduce_pair(pack2(hsum(acc0[2]), hsum(acc0[3])));
            add2(A0, xgb01[s][m]); add2(B0, xgb23[s][m]);
            float a1 = gate_act(A1, B1, sl, km, kb);
            h1v = cell_from_act(a1, c1, false);
            if (sl == 0) h1s[pp][m] = h1v;       // h1(s-1) -> parity (s-1)&1
            float a0 = gate_act(A0, B0, sl, km, kb);
            h0v = cell_from_act(a0, c0, false);
            if (sl == 0) h0s[ps][m] = h0v;       // h0(s)
            __syncthreads();
        }

        // ===== phase 8: P1(7) + in-warp pred partial
        {
            u64 acc1[4] = {0,0,0,0};
            dot64(acc1, h0s[1], wih1p, sl);      // h0(7)
            dot64(acc1, h1s[0], whh1p, sl);      // h1(6)
            u64 A1 = reduce_pair(pack2(hsum(acc1[0]), hsum(acc1[1])));
            u64 B1 = reduce_pair(pack2(hsum(acc1[2]), hsum(acc1[3])));
            add2(A1, b1p0); add2(B1, b1p1);
            float a1 = gate_act(A1, B1, sl, km, kb);
            h1v = cell_from_act(a1, c1, false);
            if (sl == 0) h1s[1][m] = h1v;
            // Wlin·h1 partial: broadcast group-lane0's h, butterfly over groups
            float hb = __shfl_sync(0xffffffffu, h1v, lane & ~3);
            float pv = wlreg * hb;
            pv += __shfl_xor_sync(0xffffffffu, pv, 4);
            pv += __shfl_xor_sync(0xffffffffu, pv, 8);
            pv += __shfl_xor_sync(0xffffffffu, pv, 16);
            if (lane < 2) predpart[wid * 2 + lane] = pv;
        }
        __syncthreads();

        // ===== phase F: finalize pred[w] (warp 7) + xgb rows 0..6 of w+1 (warps 0..6)
        if (wid < 7) {
            if (w + 1 < NW) xgb_row(w + 1, wid);
        } else if (lane < 2) {
            float d = blin_s[lane];
            #pragma unroll
            for (int k = 0; k < 8; k++) d += predpart[k * 2 + lane];
            const float prev = (w == 0) ? trajs[7 * 4 + 2 + lane]
                                        : preds[(w - 1) * 2 + lane];
            const float p = prev + d;
            preds[w * 2 + lane] = p;
            out[(b * NW + w) * 2 + lane] = p;
        }
        __syncthreads();
    }

    // ---- final states: h[2,B,H] then c[2,B,H] (valid in group lane 0) ----
    if (sl == 0) {
        const int base = BB * NW * 2;
        out[base + 0 * BB * HH + b * HH + m] = h0v;
        out[base + 1 * BB * HH + b * HH + m] = h1v;
        out[base + 2 * BB * HH + b * HH + m] = c0;
        out[base + 3 * BB * HH + b * HH + m] = c1;
    }
}

extern "C" void kernel_launch(void* const* d_in, const int* in_sizes, int n_in,
                              void* d_out, int out_size) {
    const float* traj = (const float*)d_in[0];
    const float* Wih0 = (const float*)d_in[1];
    const float* Whh0 = (const float*)d_in[2];
    const float* bih0 = (const float*)d_in[3];
    const float* bhh0 = (const float*)d_in[4];
    const float* Wih1 = (const float*)d_in[5];
    const float* Whh1 = (const float*)d_in[6];
    const float* bih1 = (const float*)d_in[7];
    const float* bhh1 = (const float*)d_in[8];
    const float* Wlin = (const float*)d_in[9];
    const float* blin = (const float*)d_in[10];

    or_lstm_kernel<<<BB, 256>>>(traj, Wih0, Whh0, bih0, bhh0,
                                Wih1, Whh1, bih1, bhh1,
                                Wlin, blin, (float*)d_out);
}